// round 2
// baseline (speedup 1.0000x reference)
#include <cuda_runtime.h>
#include <cstdint>

// PyramidROIAlign: B=?, N=?, C=256, POOL 7x7, levels p2(256) p3(128) p4(64) p5(32)
// Output [B, N, 7, 7, C] float32.
//
// One thread per float4 of output. 64 consecutive threads (c4 in [0,64)) share
// one (b, n, py, px) grid point -> warp-uniform scalar math, coalesced loads.

#define POOLH 7
#define POOLW 7
#define CCH   256
#define C4    (CCH / 4)   // 64 float4 per point

__global__ void __launch_bounds__(256) roi_align_kernel(
    const float* __restrict__ boxes,     // [B, N, 4] (y1,x1,y2,x2)
    const int*   __restrict__ image_shape, // [2]
    const float* __restrict__ p2,        // [B,256,256,C]
    const float* __restrict__ p3,        // [B,128,128,C]
    const float* __restrict__ p4,        // [B, 64, 64,C]
    const float* __restrict__ p5,        // [B, 32, 32,C]
    float*       __restrict__ out,       // [B,N,7,7,C]
    int B, int N)
{
    const long long total = (long long)B * N * POOLH * POOLW * C4;
    long long idx = (long long)blockIdx.x * blockDim.x + threadIdx.x;
    if (idx >= total) return;

    int c4  = (int)(idx & (C4 - 1));
    long long pt = idx >> 6;                  // point index: ((b*N + n)*49 + p)
    int p   = (int)(pt % (POOLH * POOLW));
    long long bn = pt / (POOLH * POOLW);
    int n   = (int)(bn % N);
    int b   = (int)(bn / N);
    int py  = p / POOLW;
    int px  = p - py * POOLW;

    // ---- box + level (warp-uniform) ----
    const float* bx = boxes + ((long long)b * N + n) * 4;
    float y1 = bx[0], x1 = bx[1], y2 = bx[2], x2 = bx[3];
    float bh = y2 - y1;
    float bw = x2 - x1;

    float img_area = (float)((long long)image_shape[0] * (long long)image_shape[1]);
    float scaled = sqrtf(bh * bw) * sqrtf(img_area) * (1.0f / 224.0f);
    float fl = rintf(log2f(scaled));
    fl = fminf(fmaxf(fl, -2.0f), 1.0f);       // clip lvl to [2,5] (== 4+fl)
    int lvl = 4 + (int)fl;

    const float* fm;
    int H;
    switch (lvl) {
        case 2:  fm = p2; H = 256; break;
        case 3:  fm = p3; H = 128; break;
        case 4:  fm = p4; H = 64;  break;
        default: fm = p5; H = 32;  break;
    }
    const int W = H;

    // ---- bilinear sample coords (match reference fp32 ops) ----
    float ty = (float)py / (float)(POOLH - 1);
    float tx = (float)px / (float)(POOLW - 1);
    float ys = (y1 + bh * ty) * (float)(H - 1);
    float xs = (x1 + bw * tx) * (float)(W - 1);

    float y0f = floorf(ys);
    float x0f = floorf(xs);
    float wy = ys - y0f;
    float wx = xs - x0f;

    int y0 = min(H - 1, max(0, (int)y0f));
    int x0 = min(W - 1, max(0, (int)x0f));
    int y1i = min(H - 1, y0 + 1);
    int x1i = min(W - 1, x0 + 1);

    // ---- gather 4 corner float4s ----
    const float4* fm4 = (const float4*)fm;
    long long base = (long long)b * H * W * C4;
    long long r0 = base + ((long long)y0  * W) * C4;
    long long r1 = base + ((long long)y1i * W) * C4;

    float4 v00 = fm4[r0 + (long long)x0  * C4 + c4];
    float4 v01 = fm4[r0 + (long long)x1i * C4 + c4];
    float4 v10 = fm4[r1 + (long long)x0  * C4 + c4];
    float4 v11 = fm4[r1 + (long long)x1i * C4 + c4];

    float4 o;
    {
        float t, bo;
        t  = v00.x + (v01.x - v00.x) * wx;
        bo = v10.x + (v11.x - v10.x) * wx;
        o.x = t + (bo - t) * wy;
        t  = v00.y + (v01.y - v00.y) * wx;
        bo = v10.y + (v11.y - v10.y) * wx;
        o.y = t + (bo - t) * wy;
        t  = v00.z + (v01.z - v00.z) * wx;
        bo = v10.z + (v11.z - v10.z) * wx;
        o.z = t + (bo - t) * wy;
        t  = v00.w + (v01.w - v00.w) * wx;
        bo = v10.w + (v11.w - v10.w) * wx;
        o.w = t + (bo - t) * wy;
    }

    ((float4*)out)[idx] = o;
}

extern "C" void kernel_launch(void* const* d_in, const int* in_sizes, int n_in,
                              void* d_out, int out_size)
{
    const float* boxes       = (const float*)d_in[0];
    const int*   image_shape = (const int*)d_in[1];
    const float* p2          = (const float*)d_in[2];
    const float* p3          = (const float*)d_in[3];
    const float* p4          = (const float*)d_in[4];
    const float* p5          = (const float*)d_in[5];
    float*       out         = (float*)d_out;

    // B from p2 element count: B * 256*256*256
    int B = in_sizes[2] / (256 * 256 * 256);
    if (B < 1) B = 1;
    int N = in_sizes[0] / (4 * B);

    long long total = (long long)B * N * POOLH * POOLW * C4;
    int threads = 256;
    long long blocks = (total + threads - 1) / threads;

    roi_align_kernel<<<(unsigned)blocks, threads>>>(
        boxes, image_shape, p2, p3, p4, p5, out, B, N);
}

// round 3
// speedup vs baseline: 1.0367x; 1.0367x over previous
#include <cuda_runtime.h>

// PyramidROIAlign, block-per-ROI formulation.
// Output [B, N, 7, 7, 256] f32. Levels: p2 256x256, p3 128x128, p4 64x64, p5 32x32.
//
// Prologue (49 threads): per-ROI level select + per-(py,px) corner offsets (int4,
// float4-granular, batch base folded in) and expanded bilinear weights (float4)
// into smem. Main loop: 3136 float4 per ROI, 256 threads, ~13 iters;
// per float4: 2 LDS.128 + 4 LDG.128 + 16 FFMA + 1 STG.128. All 32-bit indexing.

#define POOLN  49            // 7*7 grid points
#define C4V    64            // 256 channels / 4
#define PER_ROI (POOLN * C4V) // 3136 float4

__global__ void __launch_bounds__(256) roi_align_kernel(
    const float* __restrict__ boxes,       // [B,N,4]
    const int*   __restrict__ image_shape, // [2]
    const float* __restrict__ p2,
    const float* __restrict__ p3,
    const float* __restrict__ p4,
    const float* __restrict__ p5,
    float*       __restrict__ out,         // [B,N,7,7,256]
    int N)
{
    __shared__ int4   s_off[POOLN];   // corner offsets in float4 units
    __shared__ float4 s_w[POOLN];     // expanded bilinear weights
    __shared__ int    s_lvl;

    const int roi = blockIdx.x;       // b*N + n
    const int tid = threadIdx.x;
    const int b   = roi / N;

    if (tid < POOLN) {
        const float* bx = boxes + roi * 4;
        float y1 = __ldg(bx + 0), x1 = __ldg(bx + 1);
        float y2 = __ldg(bx + 2), x2 = __ldg(bx + 3);
        float bh = y2 - y1, bw = x2 - x1;

        float img_area = (float)image_shape[0] * (float)image_shape[1];
        float scaled = sqrtf(bh * bw) * sqrtf(img_area) * (1.0f / 224.0f);
        float fl = rintf(log2f(scaled));
        fl = fminf(fmaxf(fl, -2.0f), 1.0f);     // lvl = 4+fl clipped to [2,5]
        int lvl = 4 + (int)fl;
        int H = 256 >> (lvl - 2);               // 256,128,64,32
        int W = H;

        int py = tid / 7;
        int px = tid - py * 7;
        float ty = (float)py * (1.0f / 6.0f);
        float tx = (float)px * (1.0f / 6.0f);
        float ys = (y1 + bh * ty) * (float)(H - 1);
        float xs = (x1 + bw * tx) * (float)(W - 1);

        float y0f = floorf(ys);
        float x0f = floorf(xs);
        float wy = ys - y0f;
        float wx = xs - x0f;

        int y0  = min(H - 1, max(0, (int)y0f));
        int x0  = min(W - 1, max(0, (int)x0f));
        int y1i = min(H - 1, y0 + 1);
        int x1i = min(W - 1, x0 + 1);

        int base = b * H * W * C4V;             // fits int32 (max 33.5M)
        int r0 = base + y0  * W * C4V;
        int r1 = base + y1i * W * C4V;
        s_off[tid] = make_int4(r0 + x0  * C4V,
                               r0 + x1i * C4V,
                               r1 + x0  * C4V,
                               r1 + x1i * C4V);

        float iwy = 1.0f - wy, iwx = 1.0f - wx;
        s_w[tid] = make_float4(iwy * iwx, iwy * wx, wy * iwx, wy * wx);

        if (tid == 0) s_lvl = lvl;
    }
    __syncthreads();

    const int lvl = s_lvl;
    const float4* __restrict__ fm4 =
        (lvl == 2) ? (const float4*)p2 :
        (lvl == 3) ? (const float4*)p3 :
        (lvl == 4) ? (const float4*)p4 : (const float4*)p5;

    float4* __restrict__ out4 = (float4*)out + (long long)roi * PER_ROI;

    #pragma unroll 2
    for (int i = tid; i < PER_ROI; i += 256) {
        int p = i >> 6;          // point 0..48
        int c = i & (C4V - 1);   // channel quad 0..63

        int4   off = s_off[p];
        float4 w   = s_w[p];

        float4 v00 = fm4[off.x + c];
        float4 v01 = fm4[off.y + c];
        float4 v10 = fm4[off.z + c];
        float4 v11 = fm4[off.w + c];

        float4 o;
        o.x = w.x * v00.x + w.y * v01.x + w.z * v10.x + w.w * v11.x;
        o.y = w.x * v00.y + w.y * v01.y + w.z * v10.y + w.w * v11.y;
        o.z = w.x * v00.z + w.y * v01.z + w.z * v10.z + w.w * v11.z;
        o.w = w.x * v00.w + w.y * v01.w + w.z * v10.w + w.w * v11.w;

        out4[i] = o;
    }
}

extern "C" void kernel_launch(void* const* d_in, const int* in_sizes, int n_in,
                              void* d_out, int out_size)
{
    const float* boxes       = (const float*)d_in[0];
    const int*   image_shape = (const int*)d_in[1];
    const float* p2          = (const float*)d_in[2];
    const float* p3          = (const float*)d_in[3];
    const float* p4          = (const float*)d_in[4];
    const float* p5          = (const float*)d_in[5];
    float*       out         = (float*)d_out;

    int B = in_sizes[2] / (256 * 256 * 256);
    if (B < 1) B = 1;
    int N = in_sizes[0] / (4 * B);

    roi_align_kernel<<<B * N, 256>>>(boxes, image_shape, p2, p3, p4, p5, out, N);
}

// round 4
// speedup vs baseline: 1.1769x; 1.1352x over previous
#include <cuda_runtime.h>

// PyramidROIAlign, block-per-ROI, warp-per-pool-point with 256-bit loads.
// Output [B, N, 7, 7, 256] f32. Levels: p2 256x256, p3 128x128, p4 64x64, p5 32x32.
//
// Prologue (49 threads): per-ROI level select + per-point corner offsets (int4,
// float4 units, batch base folded in) + expanded bilinear weights (float4) in smem.
// Main loop: each warp owns whole pool points (all 256 channels): lane l loads
// 32 B (8 floats) per corner via ld.global.v8.f32 -> 4 LDG.256 per point,
// 32 FFMA, 2 STG.128.

#define POOLN   49
#define C4V     64
#define PER_ROI (POOLN * C4V)

__global__ void __launch_bounds__(256) roi_align_kernel(
    const float* __restrict__ boxes,       // [B,N,4]
    const int*   __restrict__ image_shape, // [2]
    const float* __restrict__ p2,
    const float* __restrict__ p3,
    const float* __restrict__ p4,
    const float* __restrict__ p5,
    float*       __restrict__ out,         // [B,N,7,7,256]
    int N)
{
    __shared__ int4   s_off[POOLN];
    __shared__ float4 s_w[POOLN];
    __shared__ int    s_lvl;

    const int roi  = blockIdx.x;           // b*N + n
    const int tid  = threadIdx.x;
    const int b    = roi / N;

    if (tid < POOLN) {
        const float* bx = boxes + roi * 4;
        float y1 = __ldg(bx + 0), x1 = __ldg(bx + 1);
        float y2 = __ldg(bx + 2), x2 = __ldg(bx + 3);
        float bh = y2 - y1, bw = x2 - x1;

        float img_area = (float)image_shape[0] * (float)image_shape[1];
        float scaled = sqrtf(bh * bw) * sqrtf(img_area) * (1.0f / 224.0f);
        float fl = rintf(log2f(scaled));
        fl = fminf(fmaxf(fl, -2.0f), 1.0f);     // lvl = 4+fl in [2,5]
        int lvl = 4 + (int)fl;
        int H = 256 >> (lvl - 2);
        int W = H;

        int py = tid / 7;
        int px = tid - py * 7;
        float ty = (float)py * (1.0f / 6.0f);
        float tx = (float)px * (1.0f / 6.0f);
        float ys = (y1 + bh * ty) * (float)(H - 1);
        float xs = (x1 + bw * tx) * (float)(W - 1);

        float y0f = floorf(ys);
        float x0f = floorf(xs);
        float wy = ys - y0f;
        float wx = xs - x0f;

        int y0  = min(H - 1, max(0, (int)y0f));
        int x0  = min(W - 1, max(0, (int)x0f));
        int y1i = min(H - 1, y0 + 1);
        int x1i = min(W - 1, x0 + 1);

        int base = b * H * W * C4V;             // float4 units, fits int32
        int r0 = base + y0  * W * C4V;
        int r1 = base + y1i * W * C4V;
        s_off[tid] = make_int4(r0 + x0  * C4V,
                               r0 + x1i * C4V,
                               r1 + x0  * C4V,
                               r1 + x1i * C4V);

        float iwy = 1.0f - wy, iwx = 1.0f - wx;
        s_w[tid] = make_float4(iwy * iwx, iwy * wx, wy * iwx, wy * wx);

        if (tid == 0) s_lvl = lvl;
    }
    __syncthreads();

    const int lvl = s_lvl;
    const float* __restrict__ fm =
        (lvl == 2) ? p2 : (lvl == 3) ? p3 : (lvl == 4) ? p4 : p5;

    const int lane = tid & 31;
    const int wid  = tid >> 5;
    float* __restrict__ outp = out + (long long)roi * (PER_ROI * 4);
    const int laneF = lane << 3;            // 8 floats per lane

    for (int pt = wid; pt < POOLN; pt += 8) {
        int4   off = s_off[pt];
        float4 w   = s_w[pt];

        const float* a00 = fm + (((long long)off.x) << 2) + laneF;
        const float* a01 = fm + (((long long)off.y) << 2) + laneF;
        const float* a10 = fm + (((long long)off.z) << 2) + laneF;
        const float* a11 = fm + (((long long)off.w) << 2) + laneF;

        float A0,A1,A2,A3,A4,A5,A6,A7;
        float B0,B1,B2,B3,B4,B5,B6,B7;
        float C0,C1,C2,C3,C4,C5,C6,C7;
        float D0,D1,D2,D3,D4,D5,D6,D7;

        asm volatile("ld.global.v8.f32 {%0,%1,%2,%3,%4,%5,%6,%7}, [%8];"
            : "=f"(A0),"=f"(A1),"=f"(A2),"=f"(A3),
              "=f"(A4),"=f"(A5),"=f"(A6),"=f"(A7) : "l"(a00));
        asm volatile("ld.global.v8.f32 {%0,%1,%2,%3,%4,%5,%6,%7}, [%8];"
            : "=f"(B0),"=f"(B1),"=f"(B2),"=f"(B3),
              "=f"(B4),"=f"(B5),"=f"(B6),"=f"(B7) : "l"(a01));
        asm volatile("ld.global.v8.f32 {%0,%1,%2,%3,%4,%5,%6,%7}, [%8];"
            : "=f"(C0),"=f"(C1),"=f"(C2),"=f"(C3),
              "=f"(C4),"=f"(C5),"=f"(C6),"=f"(C7) : "l"(a10));
        asm volatile("ld.global.v8.f32 {%0,%1,%2,%3,%4,%5,%6,%7}, [%8];"
            : "=f"(D0),"=f"(D1),"=f"(D2),"=f"(D3),
              "=f"(D4),"=f"(D5),"=f"(D6),"=f"(D7) : "l"(a11));

        float4 o0, o1;
        o0.x = w.x*A0 + w.y*B0 + w.z*C0 + w.w*D0;
        o0.y = w.x*A1 + w.y*B1 + w.z*C1 + w.w*D1;
        o0.z = w.x*A2 + w.y*B2 + w.z*C2 + w.w*D2;
        o0.w = w.x*A3 + w.y*B3 + w.z*C3 + w.w*D3;
        o1.x = w.x*A4 + w.y*B4 + w.z*C4 + w.w*D4;
        o1.y = w.x*A5 + w.y*B5 + w.z*C5 + w.w*D5;
        o1.z = w.x*A6 + w.y*B6 + w.z*C6 + w.w*D6;
        o1.w = w.x*A7 + w.y*B7 + w.z*C7 + w.w*D7;

        float4* o4 = (float4*)(outp + pt * 256 + laneF);
        o4[0] = o0;
        o4[1] = o1;
    }
}

extern "C" void kernel_launch(void* const* d_in, const int* in_sizes, int n_in,
                              void* d_out, int out_size)
{
    const float* boxes       = (const float*)d_in[0];
    const int*   image_shape = (const int*)d_in[1];
    const float* p2          = (const float*)d_in[2];
    const float* p3          = (const float*)d_in[3];
    const float* p4          = (const float*)d_in[4];
    const float* p5          = (const float*)d_in[5];
    float*       out         = (float*)d_out;

    int B = in_sizes[2] / (256 * 256 * 256);
    if (B < 1) B = 1;
    int N = in_sizes[0] / (4 * B);

    roi_align_kernel<<<B * N, 256>>>(boxes, image_shape, p2, p3, p4, p5, out, N);
}

// round 5
// speedup vs baseline: 1.2473x; 1.0599x over previous
#include <cuda_runtime.h>

// PyramidROIAlign, block-per-ROI (128 threads), warp-per-2-points, 256-bit loads,
// streaming (evict-first) stores. Output [B,N,7,7,256] f32.

#define POOLN   49
#define C4V     64
#define PER_ROI (POOLN * C4V)

__global__ void __launch_bounds__(128) roi_align_kernel(
    const float* __restrict__ boxes,       // [B,N,4]
    const int*   __restrict__ image_shape, // [2]
    const float* __restrict__ p2,
    const float* __restrict__ p3,
    const float* __restrict__ p4,
    const float* __restrict__ p5,
    float*       __restrict__ out,         // [B,N,7,7,256]
    int N)
{
    __shared__ int4   s_off[POOLN];
    __shared__ float4 s_w[POOLN];
    __shared__ int    s_lvl;

    const int roi = blockIdx.x;            // b*N + n
    const int tid = threadIdx.x;
    const int b   = roi / N;

    if (tid < POOLN) {
        const float* bx = boxes + roi * 4;
        float y1 = __ldg(bx + 0), x1 = __ldg(bx + 1);
        float y2 = __ldg(bx + 2), x2 = __ldg(bx + 3);
        float bh = y2 - y1, bw = x2 - x1;

        float img_area = (float)image_shape[0] * (float)image_shape[1];
        float scaled = sqrtf(bh * bw) * sqrtf(img_area) * (1.0f / 224.0f);
        float fl = rintf(log2f(scaled));
        fl = fminf(fmaxf(fl, -2.0f), 1.0f);     // lvl = 4+fl in [2,5]
        int lvl = 4 + (int)fl;
        int H = 256 >> (lvl - 2);
        int W = H;

        int py = tid / 7;
        int px = tid - py * 7;
        float ty = (float)py * (1.0f / 6.0f);
        float tx = (float)px * (1.0f / 6.0f);
        float ys = (y1 + bh * ty) * (float)(H - 1);
        float xs = (x1 + bw * tx) * (float)(W - 1);

        float y0f = floorf(ys);
        float x0f = floorf(xs);
        float wy = ys - y0f;
        float wx = xs - x0f;

        int y0  = min(H - 1, max(0, (int)y0f));
        int x0  = min(W - 1, max(0, (int)x0f));
        int y1i = min(H - 1, y0 + 1);
        int x1i = min(W - 1, x0 + 1);

        int base = b * H * W * C4V;             // float4 units, fits int32
        int r0 = base + y0  * W * C4V;
        int r1 = base + y1i * W * C4V;
        s_off[tid] = make_int4(r0 + x0  * C4V,
                               r0 + x1i * C4V,
                               r1 + x0  * C4V,
                               r1 + x1i * C4V);

        float iwy = 1.0f - wy, iwx = 1.0f - wx;
        s_w[tid] = make_float4(iwy * iwx, iwy * wx, wy * iwx, wy * wx);

        if (tid == 0) s_lvl = lvl;
    }
    __syncthreads();

    const int lvl = s_lvl;
    const float* __restrict__ fm =
        (lvl == 2) ? p2 : (lvl == 3) ? p3 : (lvl == 4) ? p4 : p5;

    const int lane  = tid & 31;
    const int wid   = tid >> 5;            // 0..3
    const int laneF = lane << 3;           // 8 floats per lane
    float* __restrict__ outp = out + (long long)roi * (PER_ROI * 4);

#define LD8(r0v,r1v,r2v,r3v,r4v,r5v,r6v,r7v,addr)                              \
    asm volatile("ld.global.v8.f32 {%0,%1,%2,%3,%4,%5,%6,%7}, [%8];"           \
        : "=f"(r0v),"=f"(r1v),"=f"(r2v),"=f"(r3v),                             \
          "=f"(r4v),"=f"(r5v),"=f"(r6v),"=f"(r7v) : "l"(addr))

#define ST4CS(addr, v)                                                         \
    asm volatile("st.global.cs.v4.f32 [%0], {%1,%2,%3,%4};"                    \
        :: "l"(addr), "f"((v).x), "f"((v).y), "f"((v).z), "f"((v).w))

    for (int pt = wid; pt < POOLN; pt += 8) {
        int  ptB = pt + 4;
        bool hasB = (ptB < POOLN);
        int  ptB_s = hasB ? ptB : pt;

        int4   offA = s_off[pt],   offB = s_off[ptB_s];
        float4 wA   = s_w[pt],     wB   = s_w[ptB_s];

        const float* a00 = fm + (((long long)offA.x) << 2) + laneF;
        const float* a01 = fm + (((long long)offA.y) << 2) + laneF;
        const float* a10 = fm + (((long long)offA.z) << 2) + laneF;
        const float* a11 = fm + (((long long)offA.w) << 2) + laneF;
        const float* b00 = fm + (((long long)offB.x) << 2) + laneF;
        const float* b01 = fm + (((long long)offB.y) << 2) + laneF;
        const float* b10 = fm + (((long long)offB.z) << 2) + laneF;
        const float* b11 = fm + (((long long)offB.w) << 2) + laneF;

        float A0,A1,A2,A3,A4,A5,A6,A7,  B0,B1,B2,B3,B4,B5,B6,B7;
        float C0,C1,C2,C3,C4,C5,C6,C7,  D0,D1,D2,D3,D4,D5,D6,D7;
        float E0,E1,E2,E3,E4,E5,E6,E7,  F0,F1,F2,F3,F4,F5,F6,F7;
        float G0,G1,G2,G3,G4,G5,G6,G7,  H0,H1,H2,H3,H4,H5,H6,H7;

        LD8(A0,A1,A2,A3,A4,A5,A6,A7, a00);
        LD8(B0,B1,B2,B3,B4,B5,B6,B7, a01);
        LD8(C0,C1,C2,C3,C4,C5,C6,C7, a10);
        LD8(D0,D1,D2,D3,D4,D5,D6,D7, a11);
        LD8(E0,E1,E2,E3,E4,E5,E6,E7, b00);
        LD8(F0,F1,F2,F3,F4,F5,F6,F7, b01);
        LD8(G0,G1,G2,G3,G4,G5,G6,G7, b10);
        LD8(H0,H1,H2,H3,H4,H5,H6,H7, b11);

        float4 oa0, oa1;
        oa0.x = wA.x*A0 + wA.y*B0 + wA.z*C0 + wA.w*D0;
        oa0.y = wA.x*A1 + wA.y*B1 + wA.z*C1 + wA.w*D1;
        oa0.z = wA.x*A2 + wA.y*B2 + wA.z*C2 + wA.w*D2;
        oa0.w = wA.x*A3 + wA.y*B3 + wA.z*C3 + wA.w*D3;
        oa1.x = wA.x*A4 + wA.y*B4 + wA.z*C4 + wA.w*D4;
        oa1.y = wA.x*A5 + wA.y*B5 + wA.z*C5 + wA.w*D5;
        oa1.z = wA.x*A6 + wA.y*B6 + wA.z*C6 + wA.w*D6;
        oa1.w = wA.x*A7 + wA.y*B7 + wA.z*C7 + wA.w*D7;

        float* oA = outp + pt * 256 + laneF;
        ST4CS(oA,     oa0);
        ST4CS(oA + 4, oa1);

        if (hasB) {
            float4 ob0, ob1;
            ob0.x = wB.x*E0 + wB.y*F0 + wB.z*G0 + wB.w*H0;
            ob0.y = wB.x*E1 + wB.y*F1 + wB.z*G1 + wB.w*H1;
            ob0.z = wB.x*E2 + wB.y*F2 + wB.z*G2 + wB.w*H2;
            ob0.w = wB.x*E3 + wB.y*F3 + wB.z*G3 + wB.w*H3;
            ob1.x = wB.x*E4 + wB.y*F4 + wB.z*G4 + wB.w*H4;
            ob1.y = wB.x*E5 + wB.y*F5 + wB.z*G5 + wB.w*H5;
            ob1.z = wB.x*E6 + wB.y*F6 + wB.z*G6 + wB.w*H6;
            ob1.w = wB.x*E7 + wB.y*F7 + wB.z*G7 + wB.w*H7;

            float* oB = outp + ptB * 256 + laneF;
            ST4CS(oB,     ob0);
            ST4CS(oB + 4, ob1);
        }
    }
#undef LD8
#undef ST4CS
}

extern "C" void kernel_launch(void* const* d_in, const int* in_sizes, int n_in,
                              void* d_out, int out_size)
{
    const float* boxes       = (const float*)d_in[0];
    const int*   image_shape = (const int*)d_in[1];
    const float* p2          = (const float*)d_in[2];
    const float* p3          = (const float*)d_in[3];
    const float* p4          = (const float*)d_in[4];
    const float* p5          = (const float*)d_in[5];
    float*       out         = (float*)d_out;

    int B = in_sizes[2] / (256 * 256 * 256);
    if (B < 1) B = 1;
    int N = in_sizes[0] / (4 * B);

    roi_align_kernel<<<B * N, 128>>>(boxes, image_shape, p2, p3, p4, p5, out, N);
}

// round 7
// speedup vs baseline: 1.2982x; 1.0408x over previous
#include <cuda_runtime.h>

// PyramidROIAlign, block-per-ROI (128 threads), warp-per-2-points.
// Corner vectors (1 KB each) loaded as 2 coalesced LDG.128 halves per corner
// (avoids the within-LDG wavefront replay penalty of 256-bit loads).
// Streaming (.cs) stores. Output [B,N,7,7,256] f32.

#define POOLN   49
#define C4V     64
#define PER_ROI (POOLN * C4V)

__device__ __forceinline__ float4 bilin4(float4 wt, float4 a, float4 b,
                                         float4 c, float4 d)
{
    float4 o;
    o.x = wt.x * a.x + wt.y * b.x + wt.z * c.x + wt.w * d.x;
    o.y = wt.x * a.y + wt.y * b.y + wt.z * c.y + wt.w * d.y;
    o.z = wt.x * a.z + wt.y * b.z + wt.z * c.z + wt.w * d.z;
    o.w = wt.x * a.w + wt.y * b.w + wt.z * c.w + wt.w * d.w;
    return o;
}

__device__ __forceinline__ void st4cs(float4* addr, float4 v)
{
    asm volatile("st.global.cs.v4.f32 [%0], {%1,%2,%3,%4};"
        :: "l"(addr), "f"(v.x), "f"(v.y), "f"(v.z), "f"(v.w));
}

__global__ void __launch_bounds__(128) roi_align_kernel(
    const float* __restrict__ boxes,       // [B,N,4]
    const int*   __restrict__ image_shape, // [2]
    const float* __restrict__ p2,
    const float* __restrict__ p3,
    const float* __restrict__ p4,
    const float* __restrict__ p5,
    float*       __restrict__ out,         // [B,N,7,7,256]
    int N)
{
    __shared__ int4   s_off[POOLN];
    __shared__ float4 s_w[POOLN];
    __shared__ int    s_lvl;

    const int roi = blockIdx.x;            // b*N + n
    const int tid = threadIdx.x;
    const int b   = roi / N;

    if (tid < POOLN) {
        const float* bx = boxes + roi * 4;
        float y1 = __ldg(bx + 0), x1 = __ldg(bx + 1);
        float y2 = __ldg(bx + 2), x2 = __ldg(bx + 3);
        float bh = y2 - y1, bw = x2 - x1;

        float img_area = (float)image_shape[0] * (float)image_shape[1];
        float scaled = sqrtf(bh * bw) * sqrtf(img_area) * (1.0f / 224.0f);
        float fl = rintf(log2f(scaled));
        fl = fminf(fmaxf(fl, -2.0f), 1.0f);     // lvl = 4+fl in [2,5]
        int lvl = 4 + (int)fl;
        int H = 256 >> (lvl - 2);
        int W = H;

        int py = tid / 7;
        int px = tid - py * 7;
        float ty = (float)py * (1.0f / 6.0f);
        float tx = (float)px * (1.0f / 6.0f);
        float ys = (y1 + bh * ty) * (float)(H - 1);
        float xs = (x1 + bw * tx) * (float)(W - 1);

        float y0f = floorf(ys);
        float x0f = floorf(xs);
        float wy = ys - y0f;
        float wx = xs - x0f;

        int y0  = min(H - 1, max(0, (int)y0f));
        int x0  = min(W - 1, max(0, (int)x0f));
        int y1i = min(H - 1, y0 + 1);
        int x1i = min(W - 1, x0 + 1);

        int base = b * H * W * C4V;             // float4 units, fits int32
        int r0 = base + y0  * W * C4V;
        int r1 = base + y1i * W * C4V;
        s_off[tid] = make_int4(r0 + x0  * C4V,
                               r0 + x1i * C4V,
                               r1 + x0  * C4V,
                               r1 + x1i * C4V);

        float iwy = 1.0f - wy, iwx = 1.0f - wx;
        s_w[tid] = make_float4(iwy * iwx, iwy * wx, wy * iwx, wy * wx);

        if (tid == 0) s_lvl = lvl;
    }
    __syncthreads();

    const int lvl = s_lvl;
    const float4* __restrict__ fm4 =
        (lvl == 2) ? (const float4*)p2 :
        (lvl == 3) ? (const float4*)p3 :
        (lvl == 4) ? (const float4*)p4 : (const float4*)p5;

    const int lane = tid & 31;
    const int wid  = tid >> 5;             // 0..3
    float4* __restrict__ out4 = (float4*)out + (long long)roi * PER_ROI;

    for (int pt = wid; pt < POOLN; pt += 8) {
        int  ptB  = pt + 4;
        bool hasB = (ptB < POOLN);
        int  ptBs = hasB ? ptB : pt;

        int4   offA = s_off[pt],  offB = s_off[ptBs];
        float4 wA   = s_w[pt],    wB   = s_w[ptBs];

        // Point A: 8 independent LDG.128 (lo/hi 512B halves of 4 corners)
        float4 a00l = fm4[offA.x + lane];
        float4 a01l = fm4[offA.y + lane];
        float4 a10l = fm4[offA.z + lane];
        float4 a11l = fm4[offA.w + lane];
        float4 a00h = fm4[offA.x + 32 + lane];
        float4 a01h = fm4[offA.y + 32 + lane];
        float4 a10h = fm4[offA.z + 32 + lane];
        float4 a11h = fm4[offA.w + 32 + lane];

        // Point B
        float4 b00l = fm4[offB.x + lane];
        float4 b01l = fm4[offB.y + lane];
        float4 b10l = fm4[offB.z + lane];
        float4 b11l = fm4[offB.w + lane];
        float4 b00h = fm4[offB.x + 32 + lane];
        float4 b01h = fm4[offB.y + 32 + lane];
        float4 b10h = fm4[offB.z + 32 + lane];
        float4 b11h = fm4[offB.w + 32 + lane];

        float4 oAl = bilin4(wA, a00l, a01l, a10l, a11l);
        float4 oAh = bilin4(wA, a00h, a01h, a10h, a11h);

        float4* oA = out4 + pt * C4V + lane;
        st4cs(oA,      oAl);
        st4cs(oA + 32, oAh);

        if (hasB) {
            float4 oBl = bilin4(wB, b00l, b01l, b10l, b11l);
            float4 oBh = bilin4(wB, b00h, b01h, b10h, b11h);

            float4* oB = out4 + ptB * C4V + lane;
            st4cs(oB,      oBl);
            st4cs(oB + 32, oBh);
        }
    }
}

extern "C" void kernel_launch(void* const* d_in, const int* in_sizes, int n_in,
                              void* d_out, int out_size)
{
    const float* boxes       = (const float*)d_in[0];
    const int*   image_shape = (const int*)d_in[1];
    const float* p2          = (const float*)d_in[2];
    const float* p3          = (const float*)d_in[3];
    const float* p4          = (const float*)d_in[4];
    const float* p5          = (const float*)d_in[5];
    float*       out         = (float*)d_out;

    int B = in_sizes[2] / (256 * 256 * 256);
    if (B < 1) B = 1;
    int N = in_sizes[0] / (4 * B);

    roi_align_kernel<<<B * N, 128>>>(boxes, image_shape, p2, p3, p4, p5, out, N);
}

// round 8
// speedup vs baseline: 1.6827x; 1.2962x over previous
#include <cuda_runtime.h>

// PyramidROIAlign, block-per-ROI (128 threads), warp-per-2-points.
// All 16 corner half-loads issued as asm-volatile LDG.128 (forces true MLP=16,
// ~100 live regs, no ptxas load serialization). Streaming (.cs) stores.
// Output [B,N,7,7,256] f32.

#define POOLN   49
#define C4V     64
#define PER_ROI (POOLN * C4V)

#define LD4(v, addr)                                                           \
    asm volatile("ld.global.nc.v4.f32 {%0,%1,%2,%3}, [%4];"                    \
        : "=f"((v).x), "=f"((v).y), "=f"((v).z), "=f"((v).w) : "l"(addr))

__device__ __forceinline__ float4 bilin4(float4 wt, float4 a, float4 b,
                                         float4 c, float4 d)
{
    float4 o;
    o.x = wt.x * a.x + wt.y * b.x + wt.z * c.x + wt.w * d.x;
    o.y = wt.x * a.y + wt.y * b.y + wt.z * c.y + wt.w * d.y;
    o.z = wt.x * a.z + wt.y * b.z + wt.z * c.z + wt.w * d.z;
    o.w = wt.x * a.w + wt.y * b.w + wt.z * c.w + wt.w * d.w;
    return o;
}

__device__ __forceinline__ void st4cs(float4* addr, float4 v)
{
    asm volatile("st.global.cs.v4.f32 [%0], {%1,%2,%3,%4};"
        :: "l"(addr), "f"(v.x), "f"(v.y), "f"(v.z), "f"(v.w));
}

__global__ void __launch_bounds__(128, 4) roi_align_kernel(
    const float* __restrict__ boxes,       // [B,N,4]
    const int*   __restrict__ image_shape, // [2]
    const float* __restrict__ p2,
    const float* __restrict__ p3,
    const float* __restrict__ p4,
    const float* __restrict__ p5,
    float*       __restrict__ out,         // [B,N,7,7,256]
    int N)
{
    __shared__ int4   s_off[POOLN];
    __shared__ float4 s_w[POOLN];
    __shared__ int    s_lvl;

    const int roi = blockIdx.x;            // b*N + n
    const int tid = threadIdx.x;
    const int b   = roi / N;

    if (tid < POOLN) {
        const float* bx = boxes + roi * 4;
        float y1 = __ldg(bx + 0), x1 = __ldg(bx + 1);
        float y2 = __ldg(bx + 2), x2 = __ldg(bx + 3);
        float bh = y2 - y1, bw = x2 - x1;

        float img_area = (float)image_shape[0] * (float)image_shape[1];
        float scaled = sqrtf(bh * bw) * sqrtf(img_area) * (1.0f / 224.0f);
        float fl = rintf(log2f(scaled));
        fl = fminf(fmaxf(fl, -2.0f), 1.0f);     // lvl = 4+fl in [2,5]
        int lvl = 4 + (int)fl;
        int H = 256 >> (lvl - 2);
        int W = H;

        int py = tid / 7;
        int px = tid - py * 7;
        float ty = (float)py * (1.0f / 6.0f);
        float tx = (float)px * (1.0f / 6.0f);
        float ys = (y1 + bh * ty) * (float)(H - 1);
        float xs = (x1 + bw * tx) * (float)(W - 1);

        float y0f = floorf(ys);
        float x0f = floorf(xs);
        float wy = ys - y0f;
        float wx = xs - x0f;

        int y0  = min(H - 1, max(0, (int)y0f));
        int x0  = min(W - 1, max(0, (int)x0f));
        int y1i = min(H - 1, y0 + 1);
        int x1i = min(W - 1, x0 + 1);

        int base = b * H * W * C4V;             // float4 units, fits int32
        int r0 = base + y0  * W * C4V;
        int r1 = base + y1i * W * C4V;
        s_off[tid] = make_int4(r0 + x0  * C4V,
                               r0 + x1i * C4V,
                               r1 + x0  * C4V,
                               r1 + x1i * C4V);

        float iwy = 1.0f - wy, iwx = 1.0f - wx;
        s_w[tid] = make_float4(iwy * iwx, iwy * wx, wy * iwx, wy * wx);

        if (tid == 0) s_lvl = lvl;
    }
    __syncthreads();

    const int lvl = s_lvl;
    const float4* __restrict__ fm4 =
        (lvl == 2) ? (const float4*)p2 :
        (lvl == 3) ? (const float4*)p3 :
        (lvl == 4) ? (const float4*)p4 : (const float4*)p5;

    const int lane = tid & 31;
    const int wid  = tid >> 5;             // 0..3
    float4* __restrict__ out4 = (float4*)out + (long long)roi * PER_ROI;

    for (int pt = wid; pt < POOLN; pt += 8) {
        int  ptB  = pt + 4;
        bool hasB = (ptB < POOLN);
        int  ptBs = hasB ? ptB : pt;

        int4   offA = s_off[pt],  offB = s_off[ptBs];
        float4 wA   = s_w[pt],    wB   = s_w[ptBs];

        const float4* pa0 = fm4 + offA.x + lane;
        const float4* pa1 = fm4 + offA.y + lane;
        const float4* pa2 = fm4 + offA.z + lane;
        const float4* pa3 = fm4 + offA.w + lane;
        const float4* pb0 = fm4 + offB.x + lane;
        const float4* pb1 = fm4 + offB.y + lane;
        const float4* pb2 = fm4 + offB.z + lane;
        const float4* pb3 = fm4 + offB.w + lane;

        float4 a00l, a01l, a10l, a11l, a00h, a01h, a10h, a11h;
        float4 b00l, b01l, b10l, b11l, b00h, b01h, b10h, b11h;

        // 16 back-to-back independent LDG.128 — true MLP 16
        LD4(a00l, pa0);      LD4(a01l, pa1);
        LD4(a10l, pa2);      LD4(a11l, pa3);
        LD4(a00h, pa0 + 32); LD4(a01h, pa1 + 32);
        LD4(a10h, pa2 + 32); LD4(a11h, pa3 + 32);
        LD4(b00l, pb0);      LD4(b01l, pb1);
        LD4(b10l, pb2);      LD4(b11l, pb3);
        LD4(b00h, pb0 + 32); LD4(b01h, pb1 + 32);
        LD4(b10h, pb2 + 32); LD4(b11h, pb3 + 32);

        float4 oAl = bilin4(wA, a00l, a01l, a10l, a11l);
        float4 oAh = bilin4(wA, a00h, a01h, a10h, a11h);

        float4* oA = out4 + pt * C4V + lane;
        st4cs(oA,      oAl);
        st4cs(oA + 32, oAh);

        if (hasB) {
            float4 oBl = bilin4(wB, b00l, b01l, b10l, b11l);
            float4 oBh = bilin4(wB, b00h, b01h, b10h, b11h);

            float4* oB = out4 + ptB * C4V + lane;
            st4cs(oB,      oBl);
            st4cs(oB + 32, oBh);
        }
    }
}

extern "C" void kernel_launch(void* const* d_in, const int* in_sizes, int n_in,
                              void* d_out, int out_size)
{
    const float* boxes       = (const float*)d_in[0];
    const int*   image_shape = (const int*)d_in[1];
    const float* p2          = (const float*)d_in[2];
    const float* p3          = (const float*)d_in[3];
    const float* p4          = (const float*)d_in[4];
    const float* p5          = (const float*)d_in[5];
    float*       out         = (float*)d_out;

    int B = in_sizes[2] / (256 * 256 * 256);
    if (B < 1) B = 1;
    int N = in_sizes[0] / (4 * B);

    roi_align_kernel<<<B * N, 128>>>(boxes, image_shape, p2, p3, p4, p5, out, N);
}